// round 2
// baseline (speedup 1.0000x reference)
#include <cuda_runtime.h>
#include <math.h>

#define BATCH 8
#define SEQ   1024
#define HID   768
#define INNER 64
#define ENT   9
#define NEGC  1000000000000.0f

// ---------------- scratch (device globals; no allocation allowed) ----------------
__device__ float g_q[BATCH * SEQ * INNER];       // rope'd q, [row][64]
__device__ float g_k[BATCH * SEQ * INNER];       // rope'd k, [row][64]
__device__ float g_be[BATCH * ENT * SEQ];        // bias even (col/n bias)
__device__ float g_bo[BATCH * ENT * SEQ];        // bias odd  (row/m bias)

// =====================================================================
// Kernel A1: proj = X @ w1 + b1, then RoPE -> g_q, g_k
// Tiling: BM=64 rows, BN=128 cols, BK=16. 256 threads, micro-tile 8m x 4n.
// Each thread owns 4 consecutive output cols (4i..4i+3) = one (q,k) rope pair.
// =====================================================================
__global__ __launch_bounds__(256) void k_proj(const float* __restrict__ X,
                                              const float* __restrict__ w1,
                                              const float* __restrict__ b1)
{
    __shared__ __align__(16) float As[16][68];    // [k][m], padded
    __shared__ __align__(16) float Bs[16][128];   // [k][n]

    const int tid = threadIdx.x;
    const int rowBase = blockIdx.x * 64;

    // global-load mapping
    const int lm = tid >> 2;            // 0..63 (row in tile)
    const int lk = (tid & 3) << 2;      // 0,4,8,12 (k offset)
    const float* Xrow = X + (size_t)(rowBase + lm) * HID + lk;

    // compute mapping
    const int nthr = tid & 31;          // pair index i
    const int mthr = tid >> 5;
    const int n0 = nthr << 2;
    const int m0 = mthr << 3;

    float acc[8][4];
#pragma unroll
    for (int mi = 0; mi < 8; ++mi)
#pragma unroll
        for (int ni = 0; ni < 4; ++ni) acc[mi][ni] = 0.f;

    const int wi0 = tid, wi1 = tid + 256;
    // prefetch chunk 0
    float4 xa  = *(const float4*)(Xrow);
    float4 wv0 = *(const float4*)&w1[(wi0 >> 5) * 128 + (wi0 & 31) * 4];
    float4 wv1 = *(const float4*)&w1[(wi1 >> 5) * 128 + (wi1 & 31) * 4];

    for (int kc = 0; kc < HID / 16; ++kc) {
        __syncthreads();
        As[lk + 0][lm] = xa.x;
        As[lk + 1][lm] = xa.y;
        As[lk + 2][lm] = xa.z;
        As[lk + 3][lm] = xa.w;
        *(float4*)&Bs[wi0 >> 5][(wi0 & 31) * 4] = wv0;
        *(float4*)&Bs[wi1 >> 5][(wi1 & 31) * 4] = wv1;
        __syncthreads();

        if (kc + 1 < HID / 16) {        // prefetch next chunk (hide LDG latency)
            xa  = *(const float4*)(Xrow + (kc + 1) * 16);
            wv0 = *(const float4*)&w1[((kc + 1) * 16 + (wi0 >> 5)) * 128 + (wi0 & 31) * 4];
            wv1 = *(const float4*)&w1[((kc + 1) * 16 + (wi1 >> 5)) * 128 + (wi1 & 31) * 4];
        }

#pragma unroll
        for (int kk = 0; kk < 16; ++kk) {
            float4 a0 = *(const float4*)(&As[kk][m0]);
            float4 a1 = *(const float4*)(&As[kk][m0 + 4]);
            float4 bv = *(const float4*)(&Bs[kk][n0]);
            float am[8] = {a0.x, a0.y, a0.z, a0.w, a1.x, a1.y, a1.z, a1.w};
            float bn[4] = {bv.x, bv.y, bv.z, bv.w};
#pragma unroll
            for (int mi = 0; mi < 8; ++mi)
#pragma unroll
                for (int ni = 0; ni < 4; ++ni)
                    acc[mi][ni] = fmaf(am[mi], bn[ni], acc[mi][ni]);
        }
    }

    // epilogue: bias + RoPE. pair index i = nthr
    const int i = nthr;
    const float invf = powf(10000.0f, -(float)i * (1.0f / 32.0f));
    const float4 b1v = *(const float4*)&b1[n0];

#pragma unroll
    for (int mi = 0; mi < 8; ++mi) {
        const int r = rowBase + m0 + mi;
        const int pos = r & (SEQ - 1);
        float sv, cv;
        sincosf((float)pos * invf, &sv, &cv);
        const float q0 = acc[mi][0] + b1v.x;   // proj col 4i   -> q[2i]
        const float k0 = acc[mi][1] + b1v.y;   // proj col 4i+1 -> k[2i]
        const float q1 = acc[mi][2] + b1v.z;   // proj col 4i+2 -> q[2i+1]
        const float k1 = acc[mi][3] + b1v.w;   // proj col 4i+3 -> k[2i+1]
        float2 qo = make_float2(fmaf(q0, cv, -q1 * sv), fmaf(q1, cv, q0 * sv));
        float2 ko = make_float2(fmaf(k0, cv, -k1 * sv), fmaf(k1, cv, k0 * sv));
        ((float2*)g_q)[(r << 5) + i] = qo;
        ((float2*)g_k)[(r << 5) + i] = ko;
    }
}

// =====================================================================
// Kernel A2: bias = (X @ w2 + b2) / 2, scattered to g_be / g_bo
// 64 rows/block, 256 threads = 64 rows x 4 k-splits. 6 chunks of 128 k.
// =====================================================================
__global__ __launch_bounds__(256) void k_bias(const float* __restrict__ X,
                                              const float* __restrict__ w2,
                                              const float* __restrict__ b2)
{
    __shared__ __align__(16) float sA[64 * 129];  // X chunk [64 r][128 k] (stride 129); reused as reduction buf
    __shared__ float sW[128 * 18];                // w2 chunk

    const int tid = threadIdx.x;
    const int r = tid & 63;
    const int s = tid >> 6;                       // k-split 0..3
    const int rowBase = blockIdx.x * 64;

    float acc[18];
#pragma unroll
    for (int e = 0; e < 18; ++e) acc[e] = 0.f;

    for (int kc = 0; kc < 6; ++kc) {
        __syncthreads();
        for (int i = tid; i < 64 * 32; i += 256) {          // 64 rows x 32 float4
            int rr = i >> 5, j4 = (i & 31) << 2;
            float4 v = *(const float4*)&X[(size_t)(rowBase + rr) * HID + kc * 128 + j4];
            sA[rr * 129 + j4 + 0] = v.x;
            sA[rr * 129 + j4 + 1] = v.y;
            sA[rr * 129 + j4 + 2] = v.z;
            sA[rr * 129 + j4 + 3] = v.w;
        }
        for (int i = tid; i < 128 * 18; i += 256)
            sW[i] = w2[(size_t)(kc * 128) * 18 + i];
        __syncthreads();

        const int kb = s * 32;
#pragma unroll 4
        for (int kk = 0; kk < 32; ++kk) {
            float xv = sA[r * 129 + kb + kk];
            const float* wrow = &sW[(kb + kk) * 18];
#pragma unroll
            for (int e = 0; e < 18; ++e) acc[e] = fmaf(xv, wrow[e], acc[e]);
        }
    }

    __syncthreads();
#pragma unroll
    for (int e = 0; e < 18; ++e) sA[(s * 64 + r) * 19 + e] = acc[e];
    __syncthreads();

    for (int i = tid; i < 64 * 18; i += 256) {
        int rr = i / 18, e = i - rr * 18;
        float sum = sA[rr * 19 + e] + sA[(64 + rr) * 19 + e] +
                    sA[(128 + rr) * 19 + e] + sA[(192 + rr) * 19 + e];
        float val = (sum + b2[e]) * 0.5f;
        int row = rowBase + rr;
        int bb = row >> 10, nn = row & (SEQ - 1);
        int h = e >> 1;
        if ((e & 1) == 0) g_be[(bb * ENT + h) * SEQ + nn] = val;
        else              g_bo[(bb * ENT + h) * SEQ + nn] = val;
    }
}

// =====================================================================
// Kernel B: out[b,e,m,n] = (qk/8)*mr*mc + (negr*mc + negc + tril) + mr*mc*(be+bo)
// Tile: 128 m x 64 n per block, 256 threads, micro-tile 8m x 4n,
// d-dimension processed in 2 chunks of 32 to keep smem < 48KB.
// =====================================================================
__global__ __launch_bounds__(256) void k_out(const float* __restrict__ mask,
                                             float* __restrict__ out)
{
    __shared__ __align__(16) float qs[128][36];   // [m][d-chunk], padded
    __shared__ __align__(16) float kt[32][68];    // [d][n], transposed, padded
    __shared__ __align__(16) float bes[ENT * 64];
    __shared__ __align__(16) float bos[ENT * 128];
    __shared__ __align__(16) float mrow[128];
    __shared__ __align__(16) float mcol[64];

    const int tid = threadIdx.x;
    const int nBase = blockIdx.x * 64;
    const int mBase = blockIdx.y * 128;
    const int b = blockIdx.z;
    const int bOff = b * SEQ;

    const int n0 = (tid & 15) << 2;               // 0..60
    const int m0 = (tid >> 4) << 3;               // 0..120

    // bias + mask tiles (complete before first barrier)
    for (int i = tid; i < ENT * 64; i += 256)
        bes[i] = g_be[(b * ENT + (i >> 6)) * SEQ + nBase + (i & 63)];
    for (int i = tid; i < ENT * 128; i += 256)
        bos[i] = g_bo[(b * ENT + (i >> 7)) * SEQ + mBase + (i & 127)];
    for (int i = tid; i < 128; i += 256) mrow[i] = mask[b * SEQ + mBase + i];
    if (tid < 64) mcol[tid] = mask[b * SEQ + nBase + tid];

    float acc[8][4];
#pragma unroll
    for (int mi = 0; mi < 8; ++mi)
#pragma unroll
        for (int ni = 0; ni < 4; ++ni) acc[mi][ni] = 0.f;

    for (int ch = 0; ch < 2; ++ch) {
        __syncthreads();
        // q tile: 128 rows x 32 d (float4)
        for (int i = tid; i < 128 * 8; i += 256) {
            int m = i >> 3, d4 = (i & 7) << 2;
            float4 v = *(const float4*)&g_q[((size_t)(bOff + mBase + m) << 6) + ch * 32 + d4];
            *(float4*)&qs[m][d4] = v;
        }
        // k tile transposed: 64 rows x 32 d
        for (int i = tid; i < 64 * 8; i += 256) {
            int n = i >> 3, d4 = (i & 7) << 2;
            float4 v = *(const float4*)&g_k[((size_t)(bOff + nBase + n) << 6) + ch * 32 + d4];
            kt[d4 + 0][n] = v.x;
            kt[d4 + 1][n] = v.y;
            kt[d4 + 2][n] = v.z;
            kt[d4 + 3][n] = v.w;
        }
        __syncthreads();

#pragma unroll 8
        for (int d = 0; d < 32; ++d) {
            float4 kv = *(const float4*)&kt[d][n0];
            float qv[8];
#pragma unroll
            for (int mi = 0; mi < 8; ++mi) qv[mi] = qs[m0 + mi][d];
#pragma unroll
            for (int mi = 0; mi < 8; ++mi) {
                acc[mi][0] = fmaf(qv[mi], kv.x, acc[mi][0]);
                acc[mi][1] = fmaf(qv[mi], kv.y, acc[mi][1]);
                acc[mi][2] = fmaf(qv[mi], kv.z, acc[mi][2]);
                acc[mi][3] = fmaf(qv[mi], kv.w, acc[mi][3]);
            }
        }
    }

    // ---- epilogue: fold scale, masks, tril into acc ----
    float mr[8];
#pragma unroll
    for (int mi = 0; mi < 8; ++mi) mr[mi] = mrow[m0 + mi];
    float4 mcv = *(const float4*)&mcol[n0];
    float mcs[4] = {mcv.x, mcv.y, mcv.z, mcv.w};

#pragma unroll
    for (int mi = 0; mi < 8; ++mi) {
        const float negr = -NEGC * (1.0f - mr[mi]);
        const int m = mBase + m0 + mi;
#pragma unroll
        for (int ni = 0; ni < 4; ++ni) {
            const float mc = mcs[ni];
            const float negc = -NEGC * (1.0f - mc);
            const int n = nBase + n0 + ni;
            const float t = (n < m) ? -NEGC : 0.0f;
            const float mrc = mr[mi] * mc;
            acc[mi][ni] = acc[mi][ni] * 0.125f * mrc + (negr * mc + negc + t);
        }
    }

    // ---- 9 output planes ----
#pragma unroll
    for (int e = 0; e < ENT; ++e) {
        float4 bev = *(const float4*)&bes[e * 64 + n0];
        float beA[4] = {bev.x, bev.y, bev.z, bev.w};
        const size_t planeRow = (size_t)(b * ENT + e) << 10;
#pragma unroll
        for (int mi = 0; mi < 8; ++mi) {
            const float bo = bos[e * 128 + m0 + mi];
            float4 o;
            o.x = acc[mi][0] + (mr[mi] * mcs[0]) * (beA[0] + bo);
            o.y = acc[mi][1] + (mr[mi] * mcs[1]) * (beA[1] + bo);
            o.z = acc[mi][2] + (mr[mi] * mcs[2]) * (beA[2] + bo);
            o.w = acc[mi][3] + (mr[mi] * mcs[3]) * (beA[3] + bo);
            *(float4*)&out[((planeRow + mBase + m0 + mi) << 10) + nBase + n0] = o;
        }
    }
}

// =====================================================================
extern "C" void kernel_launch(void* const* d_in, const int* in_sizes, int n_in,
                              void* d_out, int out_size)
{
    const float* X    = (const float*)d_in[0];   // (8,1024,768)
    const float* mask = (const float*)d_in[1];   // (8,1024)
    const float* w1   = (const float*)d_in[2];   // (768,128)
    const float* b1   = (const float*)d_in[3];   // (128,)
    const float* w2   = (const float*)d_in[4];   // (768,18)
    const float* b2   = (const float*)d_in[5];   // (18,)
    float* out = (float*)d_out;                  // (8,9,1024,1024)

    k_proj<<<128, 256>>>(X, w1, b1);
    k_bias<<<128, 256>>>(X, w2, b2);
    k_out<<<dim3(16, 8, 8), 256>>>(mask, out);
}

// round 3
// speedup vs baseline: 1.1012x; 1.1012x over previous
#include <cuda_runtime.h>
#include <math.h>

#define BATCH 8
#define SEQ   1024
#define HID   768
#define INNER 64
#define ENT   9
#define NEGC  1000000000000.0f

// ---------------- scratch (device globals; no allocation allowed) ----------------
__device__ float g_q[BATCH * SEQ * INNER];       // rope'd q, [row][64]
__device__ float g_k[BATCH * SEQ * INNER];       // rope'd k, [row][64]
__device__ float g_be[BATCH * ENT * SEQ];        // bias even (col/n bias)
__device__ float g_bo[BATCH * ENT * SEQ];        // bias odd  (row/m bias)

// =====================================================================
// Fused Kernel A: blocks 0..127 -> proj GEMM + RoPE; blocks 128..255 -> bias GEMM
// Dynamic smem (42.3KB) = max of the two layouts. 256 threads both paths.
// =====================================================================

__device__ __forceinline__ void proj_body(float* smem,
                                          const float* __restrict__ X,
                                          const float* __restrict__ w1,
                                          const float* __restrict__ b1,
                                          int blk)
{
    float* As = smem;               // [16][68]  (k-major, padded)
    float* Bs = smem + 16 * 68;     // [16][128]

    const int tid = threadIdx.x;
    const int rowBase = blk * 64;

    const int lm = tid >> 2;            // 0..63
    const int lk = (tid & 3) << 2;      // 0,4,8,12
    const float* Xrow = X + (size_t)(rowBase + lm) * HID + lk;

    const int nthr = tid & 31;          // pair index i
    const int mthr = tid >> 5;
    const int n0 = nthr << 2;
    const int m0 = mthr << 3;

    float acc[8][4];
#pragma unroll
    for (int mi = 0; mi < 8; ++mi)
#pragma unroll
        for (int ni = 0; ni < 4; ++ni) acc[mi][ni] = 0.f;

    const int wi0 = tid, wi1 = tid + 256;
    float4 xa  = *(const float4*)(Xrow);
    float4 wv0 = *(const float4*)&w1[(wi0 >> 5) * 128 + (wi0 & 31) * 4];
    float4 wv1 = *(const float4*)&w1[(wi1 >> 5) * 128 + (wi1 & 31) * 4];

    for (int kc = 0; kc < HID / 16; ++kc) {
        __syncthreads();
        As[(lk + 0) * 68 + lm] = xa.x;
        As[(lk + 1) * 68 + lm] = xa.y;
        As[(lk + 2) * 68 + lm] = xa.z;
        As[(lk + 3) * 68 + lm] = xa.w;
        *(float4*)&Bs[(wi0 >> 5) * 128 + (wi0 & 31) * 4] = wv0;
        *(float4*)&Bs[(wi1 >> 5) * 128 + (wi1 & 31) * 4] = wv1;
        __syncthreads();

        if (kc + 1 < HID / 16) {
            xa  = *(const float4*)(Xrow + (kc + 1) * 16);
            wv0 = *(const float4*)&w1[((kc + 1) * 16 + (wi0 >> 5)) * 128 + (wi0 & 31) * 4];
            wv1 = *(const float4*)&w1[((kc + 1) * 16 + (wi1 >> 5)) * 128 + (wi1 & 31) * 4];
        }

#pragma unroll
        for (int kk = 0; kk < 16; ++kk) {
            float4 a0 = *(const float4*)(&As[kk * 68 + m0]);
            float4 a1 = *(const float4*)(&As[kk * 68 + m0 + 4]);
            float4 bv = *(const float4*)(&Bs[kk * 128 + n0]);
            float am[8] = {a0.x, a0.y, a0.z, a0.w, a1.x, a1.y, a1.z, a1.w};
            float bn[4] = {bv.x, bv.y, bv.z, bv.w};
#pragma unroll
            for (int mi = 0; mi < 8; ++mi)
#pragma unroll
                for (int ni = 0; ni < 4; ++ni)
                    acc[mi][ni] = fmaf(am[mi], bn[ni], acc[mi][ni]);
        }
    }

    const int i = nthr;
    const float invf = powf(10000.0f, -(float)i * (1.0f / 32.0f));
    const float4 b1v = *(const float4*)&b1[n0];

#pragma unroll
    for (int mi = 0; mi < 8; ++mi) {
        const int r = rowBase + m0 + mi;
        const int pos = r & (SEQ - 1);
        float sv, cv;
        sincosf((float)pos * invf, &sv, &cv);
        const float q0 = acc[mi][0] + b1v.x;
        const float k0 = acc[mi][1] + b1v.y;
        const float q1 = acc[mi][2] + b1v.z;
        const float k1 = acc[mi][3] + b1v.w;
        float2 qo = make_float2(fmaf(q0, cv, -q1 * sv), fmaf(q1, cv, q0 * sv));
        float2 ko = make_float2(fmaf(k0, cv, -k1 * sv), fmaf(k1, cv, k0 * sv));
        ((float2*)g_q)[(r << 5) + i] = qo;
        ((float2*)g_k)[(r << 5) + i] = ko;
    }
}

__device__ __forceinline__ void bias_body(float* smem,
                                          const float* __restrict__ X,
                                          const float* __restrict__ w2,
                                          const float* __restrict__ b2,
                                          int blk)
{
    float* sA = smem;                 // [64][129] X chunk; reused as reduction buf
    float* sW = smem + 64 * 129;      // [128][18]

    const int tid = threadIdx.x;
    const int r = tid & 63;
    const int s = tid >> 6;           // k-split 0..3
    const int rowBase = blk * 64;

    float acc[18];
#pragma unroll
    for (int e = 0; e < 18; ++e) acc[e] = 0.f;

    for (int kc = 0; kc < 6; ++kc) {
        __syncthreads();
        for (int i = tid; i < 64 * 32; i += 256) {
            int rr = i >> 5, j4 = (i & 31) << 2;
            float4 v = *(const float4*)&X[(size_t)(rowBase + rr) * HID + kc * 128 + j4];
            sA[rr * 129 + j4 + 0] = v.x;
            sA[rr * 129 + j4 + 1] = v.y;
            sA[rr * 129 + j4 + 2] = v.z;
            sA[rr * 129 + j4 + 3] = v.w;
        }
        for (int i = tid; i < 128 * 18; i += 256)
            sW[i] = w2[(size_t)(kc * 128) * 18 + i];
        __syncthreads();

        const int kb = s * 32;
#pragma unroll 4
        for (int kk = 0; kk < 32; ++kk) {
            float xv = sA[r * 129 + kb + kk];
            const float* wrow = &sW[(kb + kk) * 18];
#pragma unroll
            for (int e = 0; e < 18; ++e) acc[e] = fmaf(xv, wrow[e], acc[e]);
        }
    }

    __syncthreads();
#pragma unroll
    for (int e = 0; e < 18; ++e) sA[(s * 64 + r) * 19 + e] = acc[e];
    __syncthreads();

    for (int i = tid; i < 64 * 18; i += 256) {
        int rr = i / 18, e = i - rr * 18;
        float sum = sA[rr * 19 + e] + sA[(64 + rr) * 19 + e] +
                    sA[(128 + rr) * 19 + e] + sA[(192 + rr) * 19 + e];
        float val = (sum + b2[e]) * 0.5f;
        int row = rowBase + rr;
        int bb = row >> 10, nn = row & (SEQ - 1);
        int h = e >> 1;
        if ((e & 1) == 0) g_be[(bb * ENT + h) * SEQ + nn] = val;
        else              g_bo[(bb * ENT + h) * SEQ + nn] = val;
    }
}

__global__ __launch_bounds__(256) void k_projbias(const float* __restrict__ X,
                                                  const float* __restrict__ w1,
                                                  const float* __restrict__ b1,
                                                  const float* __restrict__ w2,
                                                  const float* __restrict__ b2)
{
    extern __shared__ __align__(16) float smem[];
    const int bx = blockIdx.x;
    if (bx < 128) proj_body(smem, X, w1, b1, bx);
    else          bias_body(smem, X, w2, b2, bx - 128);
}

// =====================================================================
// Kernel B: out[b,e,m,n] = (qk/8)*mr*mc + (negr*mc + negc + tril) + mr*mc*(be+bo)
// Tile: 128m x 64n, 256 threads, micro-tile 8m x 4n.
// Both q and k are transposed in smem so the mainloop is 3 LDS.128 + 32 FFMA per d.
// =====================================================================
__global__ __launch_bounds__(256) void k_out(const float* __restrict__ mask,
                                             float* __restrict__ out)
{
    __shared__ __align__(16) float qt[32 * 132];  // [d][m], padded stride 132
    __shared__ __align__(16) float kt[32 * 68];   // [d][n], padded stride 68
    __shared__ __align__(16) float bes[ENT * 64];
    __shared__ __align__(16) float bos[ENT * 128];
    __shared__ __align__(16) float mrow[128];
    __shared__ __align__(16) float mcol[64];

    const int tid = threadIdx.x;
    const int nBase = blockIdx.x * 64;
    const int mBase = blockIdx.y * 128;
    const int b = blockIdx.z;
    const int bOff = b * SEQ;

    const int n0 = (tid & 15) << 2;               // 0..60
    const int m0 = (tid >> 4) << 3;               // 0..120

    for (int i = tid; i < ENT * 64; i += 256)
        bes[i] = g_be[(b * ENT + (i >> 6)) * SEQ + nBase + (i & 63)];
    for (int i = tid; i < ENT * 128; i += 256)
        bos[i] = g_bo[(b * ENT + (i >> 7)) * SEQ + mBase + (i & 127)];
    for (int i = tid; i < 128; i += 256) mrow[i] = mask[b * SEQ + mBase + i];
    if (tid < 64) mcol[tid] = mask[b * SEQ + nBase + tid];

    float acc[8][4];
#pragma unroll
    for (int mi = 0; mi < 8; ++mi)
#pragma unroll
        for (int ni = 0; ni < 4; ++ni) acc[mi][ni] = 0.f;

    for (int ch = 0; ch < 2; ++ch) {
        __syncthreads();
        // q tile transposed: 128 m x 32 d
        for (int i = tid; i < 128 * 8; i += 256) {
            int m = i >> 3, d4 = (i & 7) << 2;
            float4 v = *(const float4*)&g_q[((size_t)(bOff + mBase + m) << 6) + ch * 32 + d4];
            qt[(d4 + 0) * 132 + m] = v.x;
            qt[(d4 + 1) * 132 + m] = v.y;
            qt[(d4 + 2) * 132 + m] = v.z;
            qt[(d4 + 3) * 132 + m] = v.w;
        }
        // k tile transposed: 64 n x 32 d
        for (int i = tid; i < 64 * 8; i += 256) {
            int n = i >> 3, d4 = (i & 7) << 2;
            float4 v = *(const float4*)&g_k[((size_t)(bOff + nBase + n) << 6) + ch * 32 + d4];
            kt[(d4 + 0) * 68 + n] = v.x;
            kt[(d4 + 1) * 68 + n] = v.y;
            kt[(d4 + 2) * 68 + n] = v.z;
            kt[(d4 + 3) * 68 + n] = v.w;
        }
        __syncthreads();

#pragma unroll 8
        for (int d = 0; d < 32; ++d) {
            float4 kv = *(const float4*)&kt[d * 68 + n0];
            float4 q0 = *(const float4*)&qt[d * 132 + m0];
            float4 q1 = *(const float4*)&qt[d * 132 + m0 + 4];
            float qv[8] = {q0.x, q0.y, q0.z, q0.w, q1.x, q1.y, q1.z, q1.w};
#pragma unroll
            for (int mi = 0; mi < 8; ++mi) {
                acc[mi][0] = fmaf(qv[mi], kv.x, acc[mi][0]);
                acc[mi][1] = fmaf(qv[mi], kv.y, acc[mi][1]);
                acc[mi][2] = fmaf(qv[mi], kv.z, acc[mi][2]);
                acc[mi][3] = fmaf(qv[mi], kv.w, acc[mi][3]);
            }
        }
    }

    // ---- epilogue: fold scale, masks, tril into acc; precompute mrc ----
    float mr[8];
#pragma unroll
    for (int mi = 0; mi < 8; ++mi) mr[mi] = mrow[m0 + mi];
    float4 mcv = *(const float4*)&mcol[n0];
    float mcs[4] = {mcv.x, mcv.y, mcv.z, mcv.w};

    float mrc[8][4];
#pragma unroll
    for (int mi = 0; mi < 8; ++mi) {
        const float negr = -NEGC * (1.0f - mr[mi]);
        const int m = mBase + m0 + mi;
#pragma unroll
        for (int ni = 0; ni < 4; ++ni) {
            const float mc = mcs[ni];
            const float negc = -NEGC * (1.0f - mc);
            const int n = nBase + n0 + ni;
            const float t = (n < m) ? -NEGC : 0.0f;
            mrc[mi][ni] = mr[mi] * mc;
            acc[mi][ni] = acc[mi][ni] * 0.125f * mrc[mi][ni] + (negr * mc + negc + t);
        }
    }

    // ---- 9 output planes: 1 FADD + 1 FFMA per element ----
#pragma unroll
    for (int e = 0; e < ENT; ++e) {
        float4 bev = *(const float4*)&bes[e * 64 + n0];
        float beA[4] = {bev.x, bev.y, bev.z, bev.w};
        const size_t planeRow = (size_t)(b * ENT + e) << 10;
#pragma unroll
        for (int mi = 0; mi < 8; ++mi) {
            const float bo = bos[e * 128 + m0 + mi];
            float4 o;
            o.x = fmaf(mrc[mi][0], beA[0] + bo, acc[mi][0]);
            o.y = fmaf(mrc[mi][1], beA[1] + bo, acc[mi][1]);
            o.z = fmaf(mrc[mi][2], beA[2] + bo, acc[mi][2]);
            o.w = fmaf(mrc[mi][3], beA[3] + bo, acc[mi][3]);
            *(float4*)&out[((planeRow + mBase + m0 + mi) << 10) + nBase + n0] = o;
        }
    }
}

// =====================================================================
extern "C" void kernel_launch(void* const* d_in, const int* in_sizes, int n_in,
                              void* d_out, int out_size)
{
    const float* X    = (const float*)d_in[0];   // (8,1024,768)
    const float* mask = (const float*)d_in[1];   // (8,1024)
    const float* w1   = (const float*)d_in[2];   // (768,128)
    const float* b1   = (const float*)d_in[3];   // (128,)
    const float* w2   = (const float*)d_in[4];   // (768,18)
    const float* b2   = (const float*)d_in[5];   // (18,)
    float* out = (float*)d_out;                  // (8,9,1024,1024)

    // dynamic smem = max(bias layout, proj layout) = (64*129 + 128*18) floats
    const int smemBytes = (64 * 129 + 128 * 18) * 4;   // 42240 B
    k_projbias<<<256, 256, smemBytes>>>(X, w1, b1, w2, b2);
    k_out<<<dim3(16, 8, 8), 256>>>(mask, out);
}